// round 10
// baseline (speedup 1.0000x reference)
#include <cuda_runtime.h>
#include <cuda_fp16.h>
#include <cstdint>
#include <math.h>

#define NC      64
#define DHEAD   128
#define BATCHB  512
#define COLS    8192
#define NPAIRS  2016
#define KC      64              // k-halfs per chunk (128B row)
#define NCH     8
#define ROWB    144             // smem row stride bytes (64 halfs + 8 pad)
#define A_ST    (DHEAD * ROWB)  // 18432
#define STG     (2 * A_ST)      // 36864 per stage (A+B)
#define NSTG    3
#define SMEM_DYN (NSTG * STG)   // 110592

// fp16 of 256*q^2, transposed [gram][col][b]  (16.8 MB, L2-resident)
__device__ __half g_Xt[2ULL * COLS * BATCHB];
__device__ float  g_acc[4];

__device__ __forceinline__ float fsqrt_fast(float x) {
    float r; asm("sqrt.approx.f32 %0, %1;" : "=f"(r) : "f"(x)); return r;
}
__device__ __forceinline__ uint32_t smem_u32(const void* p) {
    uint32_t a;
    asm("{ .reg .u64 t; cvta.to.shared.u64 t, %1; cvt.u32.u64 %0, t; }" : "=r"(a) : "l"(p));
    return a;
}
#define CP16(dst, src) \
    asm volatile("cp.async.cg.shared.global [%0], [%1], 16;" :: "r"(dst), "l"(src))
#define CP_COMMIT() asm volatile("cp.async.commit_group;" ::: "memory")
#define CP_WAIT1()  asm volatile("cp.async.wait_group 1;"  ::: "memory")
#define LDSM_X4(r0, r1, r2, r3, a) \
    asm volatile("ldmatrix.sync.aligned.m8n8.x4.shared.b16 {%0,%1,%2,%3}, [%4];" \
                 : "=r"(r0), "=r"(r1), "=r"(r2), "=r"(r3) : "r"(a))

// ---------------- kernel 0 ----------------
__global__ void k_zero() { if (threadIdx.x < 4) g_acc[threadIdx.x] = 0.0f; }

// ---------------- kernel 1: softmax -> fp16 256*q^2 transposed + self-sim dot ----------------
__global__ void k_softmax(const float* __restrict__ emb) {
    const int c    = blockIdx.y;
    const int b0   = blockIdx.x * 16;
    const int w    = threadIdx.x >> 5;
    const int lane = threadIdx.x & 31;

    __shared__ __align__(16) __half sm_t[2][DHEAD][16];
    __shared__ float dotred[16];

    const int b = b0 + w;
    const float* pa = emb + (size_t)b * COLS + c * DHEAD;
    const float* pb = emb + (size_t)(b + BATCHB) * COLS + c * DHEAD;

    float xa[4], xb[4];
#pragma unroll
    for (int p = 0; p < 4; ++p) { xa[p] = pa[lane + 32 * p]; xb[p] = pb[lane + 32 * p]; }

    float ma = fmaxf(fmaxf(xa[0], xa[1]), fmaxf(xa[2], xa[3]));
    float mb = fmaxf(fmaxf(xb[0], xb[1]), fmaxf(xb[2], xb[3]));
#pragma unroll
    for (int off = 16; off > 0; off >>= 1) {
        ma = fmaxf(ma, __shfl_xor_sync(0xFFFFFFFFu, ma, off));
        mb = fmaxf(mb, __shfl_xor_sync(0xFFFFFFFFu, mb, off));
    }
    float ea[4], eb[4], sa = 0.f, sb = 0.f;
#pragma unroll
    for (int p = 0; p < 4; ++p) {
        ea[p] = __expf(xa[p] - ma); sa += ea[p];
        eb[p] = __expf(xb[p] - mb); sb += eb[p];
    }
#pragma unroll
    for (int off = 16; off > 0; off >>= 1) {
        sa += __shfl_xor_sync(0xFFFFFFFFu, sa, off);
        sb += __shfl_xor_sync(0xFFFFFFFFu, sb, off);
    }
    const float ia = 16.0f / sa, ib = 16.0f / sb;
    float dot = 0.f;
#pragma unroll
    for (int p = 0; p < 4; ++p) {
        float qa = ea[p] * ia;
        float qb = eb[p] * ib;
        dot += qa * qb;                               // 256*qa*qb
        sm_t[0][lane + 32 * p][w] = __float2half_rn(qa * qa);   // 256*q^2
        sm_t[1][lane + 32 * p][w] = __float2half_rn(qb * qb);
    }
#pragma unroll
    for (int off = 16; off > 0; off >>= 1)
        dot += __shfl_xor_sync(0xFFFFFFFFu, dot, off);
    if (lane == 0) dotred[w] = dot;
    __syncthreads();
    if (threadIdx.x == 0) {
        float s = 0.f;
#pragma unroll
        for (int k = 0; k < 16; ++k) s += dotred[k];
        atomicAdd(&g_acc[0], s * (1.0f / 256.0f));
    }
    const int tid = threadIdx.x;
    const int g = tid >> 8;
    const int d = (tid >> 1) & 127;
    const int h = tid & 1;
    uint4 v = *(const uint4*)&sm_t[g][d][h * 8];
    __half* dst = g_Xt + (size_t)g * COLS * BATCHB
                + (size_t)(c * DHEAD + d) * BATCHB + (b0 + h * 8);
    *(uint4*)dst = v;
}

// ---------------- kernel 2: 128x128 Gram tile, HMMA + ldmatrix.x4, 3-stage cp.async ----
// 8 warps 4(row)x2(col), warp tile 32x64, mma m16n8k16 f16->f32, K=512 in 8 chunks.
__global__ void __launch_bounds__(256, 2) k_gram() {
    extern __shared__ __align__(16) char dsm[];
    __shared__ float wsum[8];

    const uint32_t sbase = smem_u32(dsm);
    const int tid  = threadIdx.x;
    const int wid  = tid >> 5;
    const int lane = tid & 31;

    // pair decode: t = j*(j-1)/2 + i, i < j
    const int t = blockIdx.x;
    int j = (int)((1.0f + sqrtf(8.0f * (float)t + 1.0f)) * 0.5f);
    while (j * (j - 1) / 2 > t) --j;
    while ((j + 1) * j / 2 <= t) ++j;
    const int i = t - j * (j - 1) / 2;
    const int gram = blockIdx.y;

    const __half* xg = g_Xt + (size_t)gram * COLS * BATCHB;
    const __half* gA = xg + (size_t)j * DHEAD * BATCHB;
    const __half* gB = xg + (size_t)i * DHEAD * BATCHB;

    const int wr = (wid & 3) * 32;
    const int wc = (wid >> 2) * 64;

    // ldmatrix lane addressing: row-in-16 = lane&15, k-half select = lane>>4
    const int lrow = lane & 15;
    const uint32_t lkb = (uint32_t)(lane >> 4) * 16;    // 0 or 16 bytes (8 halfs)
    // per-lane byte offsets inside a stage
    const uint32_t aoff_l = (uint32_t)(wr + lrow) * ROWB + lkb;           // + rm*16*ROWB + ks*32
    const uint32_t boff_l = A_ST + (uint32_t)(wc + lrow) * ROWB + lkb;    // + p*16*ROWB + ks*32

    float acc[2][8][4];
#pragma unroll
    for (int a = 0; a < 2; ++a)
#pragma unroll
        for (int b = 0; b < 8; ++b)
#pragma unroll
            for (int c2 = 0; c2 < 4; ++c2) acc[a][b][c2] = 0.f;

    // chunk loader: 128 rows x 64 halfs per operand -> 8 cp.async per thread
    auto load_chunk = [&](int st, int ch) {
        const uint32_t ao = sbase + st * STG;
        const uint32_t bo = ao + A_ST;
#pragma unroll
        for (int it = 0; it < 4; ++it) {
            const int u = tid + it * 256;           // 0..1023
            const int r = u >> 3, seg = u & 7;
            const size_t goff = (size_t)r * BATCHB + ch * KC + seg * 8;
            CP16(ao + r * ROWB + seg * 16, gA + goff);
            CP16(bo + r * ROWB + seg * 16, gB + goff);
        }
        CP_COMMIT();
    };

    load_chunk(0, 0);
    load_chunk(1, 1);

#pragma unroll 1
    for (int ch = 0; ch < NCH; ++ch) {
        const uint32_t sst = sbase + (ch % NSTG) * STG;
        CP_WAIT1();
        __syncthreads();

        const uint32_t pa = sst + aoff_l;
        const uint32_t pb = sst + boff_l;

#pragma unroll
        for (int ks = 0; ks < 4; ++ks) {
            const uint32_t kb = (uint32_t)ks * 32;
            uint32_t a0[4], a1[4], bf[4][4];
            LDSM_X4(a0[0], a0[1], a0[2], a0[3], pa + kb);                 // rows wr..wr+15
            LDSM_X4(a1[0], a1[1], a1[2], a1[3], pa + 16 * ROWB + kb);     // rows wr+16..31
#pragma unroll
            for (int p = 0; p < 4; ++p)
                LDSM_X4(bf[p][0], bf[p][1], bf[p][2], bf[p][3],
                        pb + (uint32_t)p * 16 * ROWB + kb);               // cols wc+p*16..+15
#pragma unroll
            for (int p = 0; p < 4; ++p) {
#pragma unroll
                for (int s = 0; s < 2; ++s) {
                    const int cn = 2 * p + s;
                    const uint32_t b0 = bf[p][s], b1 = bf[p][s + 2];
                    asm volatile(
                        "mma.sync.aligned.m16n8k16.row.col.f32.f16.f16.f32 "
                        "{%0,%1,%2,%3}, {%4,%5,%6,%7}, {%8,%9}, {%0,%1,%2,%3};"
                        : "+f"(acc[0][cn][0]), "+f"(acc[0][cn][1]),
                          "+f"(acc[0][cn][2]), "+f"(acc[0][cn][3])
                        : "r"(a0[0]), "r"(a0[1]), "r"(a0[2]), "r"(a0[3]),
                          "r"(b0), "r"(b1));
                    asm volatile(
                        "mma.sync.aligned.m16n8k16.row.col.f32.f16.f16.f32 "
                        "{%0,%1,%2,%3}, {%4,%5,%6,%7}, {%8,%9}, {%0,%1,%2,%3};"
                        : "+f"(acc[1][cn][0]), "+f"(acc[1][cn][1]),
                          "+f"(acc[1][cn][2]), "+f"(acc[1][cn][3])
                        : "r"(a1[0]), "r"(a1[1]), "r"(a1[2]), "r"(a1[3]),
                          "r"(b0), "r"(b1));
                }
            }
        }
        if (ch + 2 < NCH) load_chunk((ch + 2) % NSTG, ch + 2);
    }

    // epilogue: sum sqrt over all accumulator entries
    float lsum = 0.f;
#pragma unroll
    for (int a = 0; a < 2; ++a)
#pragma unroll
        for (int b = 0; b < 8; ++b)
#pragma unroll
            for (int c2 = 0; c2 < 4; ++c2) lsum += fsqrt_fast(acc[a][b][c2]);
#pragma unroll
    for (int off = 16; off > 0; off >>= 1)
        lsum += __shfl_xor_sync(0xFFFFFFFFu, lsum, off);
    if (lane == 0) wsum[wid] = lsum;
    __syncthreads();
    if (tid == 0) {
        float s = 0.f;
#pragma unroll
        for (int k = 0; k < 8; ++k) s += wsum[k];
        atomicAdd(&g_acc[1 + gram], s);
    }
}

// ---------------- kernel 3: finalize ----------------
__global__ void k_final(float* __restrict__ out) {
    // operands 256*q^2 -> G x65536 -> sqrt x256. raw_g (i!=j) = 2*acc/256.
    const float scale = (float)(NC * NC - NC) * sqrtf((float)BATCHB);
    const float self = -g_acc[0] / (float)(BATCHB * NC);
    const float clus = -(2.0f * (g_acc[1] + g_acc[2]) / 256.0f) / (2.0f * scale);
    out[0] = self + clus;
}

extern "C" void kernel_launch(void* const* d_in, const int* in_sizes, int n_in,
                              void* d_out, int out_size) {
    const float* emb = (const float*)d_in[0];
    float* out = (float*)d_out;
    cudaFuncSetAttribute(k_gram, cudaFuncAttributeMaxDynamicSharedMemorySize, SMEM_DYN);
    k_zero<<<1, 32>>>();
    k_softmax<<<dim3(32, 64), 512>>>(emb);
    k_gram<<<dim3(NPAIRS, 2), 256, SMEM_DYN>>>();
    k_final<<<1, 1>>>(out);
}